// round 4
// baseline (speedup 1.0000x reference)
#include <cuda_runtime.h>
#include <cuda_bf16.h>

#define HID 20
#define NT 256
#define CPC (NT / 4)          // coords per CTA = 64
#define KPL 5                  // hidden units per lane

__device__ __forceinline__ float tanh_ap(float x) {
    float y;
    asm("tanh.approx.f32 %0, %1;" : "=f"(y) : "f"(x));
    return y;
}

// sigmoid(z) where zh = 0.5*z was computed directly (0.5 folded into weights)
__device__ __forceinline__ float sig_from_half(float zh) {
    return fmaf(0.5f, tanh_ap(zh), 0.5f);
}

__global__ void __launch_bounds__(NT, 8)
lstm_opt_kernel(const float* __restrict__ params,
                const float* __restrict__ grads,
                const float* __restrict__ h0,
                const float* __restrict__ c0,
                const float* __restrict__ W_ih,   // [80,2]
                const float* __restrict__ W_hh,   // [80,20]
                const float* __restrict__ b_ih,   // [80]
                const float* __restrict__ b_hh,   // [80]
                const float* __restrict__ W_out,  // [20]
                const float* __restrict__ b_out,  // [1]
                float* __restrict__ out,
                int n)
{
    // Reusable staging buffer: 64 rows x 20 floats (c0, then h0).
    __shared__ float sStage[CPC * HID];          // 5120 B
    // Per-k packed weights, row padded to 20 words (80B) so quad-strided
    // LDS.128 reads hit disjoint bank groups.
    // [0]=wi_g [1]=wi_p [2]=bi(h) [3]=wg_g | [4]=wg_p [5]=bg [6]=wo_g [7]=wo_p |
    // [8]=bo(h) [9]=wf_g [10]=wf_p [11]=bf(h) | [12]=W_out[k] [13..19]=pad
    __shared__ float sPack[HID][20];             // 1600 B
    __shared__ float sbo;

    const int t     = threadIdx.x;
    const int j     = t & 3;                 // lane-in-quad: hidden slice
    const int cl    = t >> 2;                // coord-local (0..63)
    const int base  = blockIdx.x * CPC;
    const int rows  = min(CPC, n - base);
    const bool active = (cl < rows);
    const int clc   = active ? cl : 0;       // clamped for safe smem reads
    const int coord = base + clc;

    // ---- stage packed weights ----
    if (t < HID) {
        const int k  = t;
        const int rf = 20 + k, rg = 40 + k, ro = 60 + k;
        sPack[k][0]  = 0.5f * W_ih[2 * k];
        sPack[k][1]  = 0.5f * W_ih[2 * k + 1];
        sPack[k][2]  = 0.5f * (b_ih[k] + b_hh[k]);
        sPack[k][3]  = W_ih[2 * rg];
        sPack[k][4]  = W_ih[2 * rg + 1];
        sPack[k][5]  = b_ih[rg] + b_hh[rg];
        sPack[k][6]  = 0.5f * W_ih[2 * ro];
        sPack[k][7]  = 0.5f * W_ih[2 * ro + 1];
        sPack[k][8]  = 0.5f * (b_ih[ro] + b_hh[ro]);
        sPack[k][9]  = 0.5f * W_ih[2 * rf];
        sPack[k][10] = 0.5f * W_ih[2 * rf + 1];
        sPack[k][11] = 0.5f * (b_ih[rf] + b_hh[rf]);
        sPack[k][12] = W_out[k];
        #pragma unroll
        for (int z = 13; z < 20; z++) sPack[k][z] = 0.0f;
    }
    if (t == 0) sbo = b_out[0];

    // scalar inputs (quad-redundant loads coalesce to the same sectors)
    float g = 0.0f, p = 0.0f;
    if (active) { g = grads[coord]; p = params[coord]; }

    // ---- stage c0 (coalesced float4), read this lane's 5 values ----
    {
        const float4* c4 = reinterpret_cast<const float4*>(c0) + (size_t)base * 5;
        float4* s4 = reinterpret_cast<float4*>(sStage);
        const int nv = rows * 5;
        for (int w = t; w < nv; w += NT) s4[w] = c4[w];
    }
    __syncthreads();

    float cv[KPL];
    {
        const float* src = sStage + clc * HID + j * KPL;   // addr = 5t+kk: conflict-free
        #pragma unroll
        for (int kk = 0; kk < KPL; kk++) cv[kk] = src[kk];
    }
    __syncthreads();

    // ---- stage h0 into the same buffer ----
    {
        const float4* h4 = reinterpret_cast<const float4*>(h0) + (size_t)base * 5;
        float4* s4 = reinterpret_cast<float4*>(sStage);
        const int nv = rows * 5;
        for (int w = t; w < nv; w += NT) s4[w] = h4[w];
    }
    __syncthreads();

    // h-row zero test: per-lane partial, reduced across the quad (uniform branch)
    float habs = 0.0f;
    {
        const float* src = sStage + clc * HID + j * KPL;
        #pragma unroll
        for (int kk = 0; kk < KPL; kk++) habs += fabsf(src[kk]);
    }
    habs += __shfl_xor_sync(0xffffffffu, habs, 1);
    habs += __shfl_xor_sync(0xffffffffu, habs, 2);
    const bool hzero = (habs == 0.0f);

    float acc = 0.0f;

    if (__builtin_expect(hzero, 1)) {
        // ---- fast path: h0 row exactly zero -> skip W_hh matvec ----
        #pragma unroll
        for (int kk = 0; kk < KPL; kk++) {
            const int k = j * KPL + kk;
            const float4* pk = reinterpret_cast<const float4*>(sPack[k]);
            float4 w0 = pk[0];   // wi_g, wi_p, bi, wg_g
            float4 w1 = pk[1];   // wg_p, bg, wo_g, wo_p
            float4 w2 = pk[2];   // bo, wf_g, wf_p, bf
            float4 w3 = pk[3];   // W_out[k], pad...

            float zi = fmaf(w0.x, g, fmaf(w0.y, p, w0.z));   // halved
            float zg = fmaf(w0.w, g, fmaf(w1.x, p, w1.y));
            float zo = fmaf(w1.z, g, fmaf(w1.w, p, w2.x));   // halved

            float ik = sig_from_half(zi);
            float gk = tanh_ap(zg);
            float ok = sig_from_half(zo);

            float c1 = ik * gk;
            float ck = cv[kk];
            if (ck != 0.0f) {
                float zf = fmaf(w2.y, g, fmaf(w2.z, p, w2.w)); // halved
                c1 = fmaf(sig_from_half(zf), ck, c1);
            }
            acc = fmaf(ok * tanh_ap(c1), w3.x, acc);
        }
    } else {
        // ---- general path: full W_hh matvec (cold; W_hh via L2, h from smem) ----
        const float* sHrow = sStage + clc * HID;
        #pragma unroll 1
        for (int kk = 0; kk < KPL; kk++) {
            const int k = j * KPL + kk;
            const float* pk = sPack[k];
            float zi = fmaf(pk[0], g, fmaf(pk[1],  p, pk[2]));   // halved
            float zg = fmaf(pk[3], g, fmaf(pk[4],  p, pk[5]));
            float zo = fmaf(pk[6], g, fmaf(pk[7],  p, pk[8]));   // halved
            float zf = fmaf(pk[9], g, fmaf(pk[10], p, pk[11]));  // halved
            const int ri = k, rf = 20 + k, rg = 40 + k, ro = 60 + k;
            #pragma unroll 1
            for (int m = 0; m < HID; m++) {
                float hm = sHrow[m];
                zi = fmaf(0.5f * __ldg(&W_hh[ri * HID + m]), hm, zi);
                zf = fmaf(0.5f * __ldg(&W_hh[rf * HID + m]), hm, zf);
                zg = fmaf(       __ldg(&W_hh[rg * HID + m]), hm, zg);
                zo = fmaf(0.5f * __ldg(&W_hh[ro * HID + m]), hm, zo);
            }
            float ik = sig_from_half(zi);
            float fk = sig_from_half(zf);
            float gk = tanh_ap(zg);
            float ok = sig_from_half(zo);
            float c1 = fmaf(fk, cv[kk], ik * gk);
            acc = fmaf(ok * tanh_ap(c1), pk[12], acc);
        }
    }

    // ---- quad reduction, lane 0 of each quad writes ----
    acc += __shfl_xor_sync(0xffffffffu, acc, 1);
    acc += __shfl_xor_sync(0xffffffffu, acc, 2);
    if (active && j == 0) out[coord] = acc + sbo;
}

extern "C" void kernel_launch(void* const* d_in, const int* in_sizes, int n_in,
                              void* d_out, int out_size)
{
    const float* params = (const float*)d_in[0];
    const float* grads  = (const float*)d_in[1];
    const float* h0     = (const float*)d_in[2];
    const float* c0     = (const float*)d_in[3];
    const float* W_ih   = (const float*)d_in[4];
    const float* W_hh   = (const float*)d_in[5];
    const float* b_ih   = (const float*)d_in[6];
    const float* b_hh   = (const float*)d_in[7];
    const float* W_out  = (const float*)d_in[8];
    const float* b_out  = (const float*)d_in[9];
    float* out = (float*)d_out;

    int n = in_sizes[0];
    int blocks = (n + CPC - 1) / CPC;
    lstm_opt_kernel<<<blocks, NT>>>(params, grads, h0, c0,
                                    W_ih, W_hh, b_ih, b_hh,
                                    W_out, b_out, out, n);
}

// round 6
// speedup vs baseline: 1.8381x; 1.8381x over previous
#include <cuda_runtime.h>
#include <cuda_bf16.h>

#define HID 20
#define NT 256

// Transformed-weight layout (261 floats):
//   [0]   wi_g*0.5   [20] wi_p*0.5  [40] (b_ih+b_hh)_i*0.5
//   [60]  wg_g       [80] wg_p      [100] (b)_g
//   [120] wo_g*0.5   [140] wo_p*0.5 [160] (b)_o*0.5
//   [180] wf_g*0.5   [200] wf_p*0.5 [220] (b)_f*0.5
//   [240] W_out      [260] b_out
#define CW_SIZE 261
__constant__ float cW[CW_SIZE];
__device__ float dPrep[CW_SIZE];

__device__ __forceinline__ float tanh_ap(float x) {
    float y;
    asm("tanh.approx.f32 %0, %1;" : "=f"(y) : "f"(x));
    return y;
}
// sigmoid(z) where zh = 0.5*z was computed with pre-halved weights
__device__ __forceinline__ float sig_from_half(float zh) {
    return fmaf(0.5f, tanh_ap(zh), 0.5f);
}

__global__ void prep_kernel(const float* __restrict__ W_ih,
                            const float* __restrict__ b_ih,
                            const float* __restrict__ b_hh,
                            const float* __restrict__ W_out,
                            const float* __restrict__ b_out)
{
    const int k = threadIdx.x;
    if (k < HID) {
        const int rf = 20 + k, rg = 40 + k, ro = 60 + k;
        dPrep[k]        = 0.5f * W_ih[2 * k];
        dPrep[20 + k]   = 0.5f * W_ih[2 * k + 1];
        dPrep[40 + k]   = 0.5f * (b_ih[k] + b_hh[k]);
        dPrep[60 + k]   = W_ih[2 * rg];
        dPrep[80 + k]   = W_ih[2 * rg + 1];
        dPrep[100 + k]  = b_ih[rg] + b_hh[rg];
        dPrep[120 + k]  = 0.5f * W_ih[2 * ro];
        dPrep[140 + k]  = 0.5f * W_ih[2 * ro + 1];
        dPrep[160 + k]  = 0.5f * (b_ih[ro] + b_hh[ro]);
        dPrep[180 + k]  = 0.5f * W_ih[2 * rf];
        dPrep[200 + k]  = 0.5f * W_ih[2 * rf + 1];
        dPrep[220 + k]  = 0.5f * (b_ih[rf] + b_hh[rf]);
        dPrep[240 + k]  = W_out[k];
    }
    if (k == 0) dPrep[260] = b_out[0];
}

__global__ void __launch_bounds__(NT, 5)
lstm_opt_kernel(const float* __restrict__ params,
                const float* __restrict__ grads,
                const float* __restrict__ h0,
                const float* __restrict__ c0,
                const float* __restrict__ W_hh,   // [80,20] (cold general path)
                float* __restrict__ out,
                int n)
{
    // Reusable staging buffer: 256 rows x 20 floats (c0 first, then h0).
    __shared__ float sStage[NT * HID];   // 20 KB

    const int t    = threadIdx.x;
    const int base = blockIdx.x * NT;
    const int rows = min(NT, n - base);
    const int nv   = rows * 5;
    const bool active = (t < rows);
    const int i = base + t;

    float g = 0.0f, p = 0.0f;
    if (active) { g = grads[i]; p = params[i]; }

    // ---- stage c0 (coalesced float4), read own row into regs ----
    {
        const float4* c4 = reinterpret_cast<const float4*>(c0) + (size_t)base * 5;
        float4* s4 = reinterpret_cast<float4*>(sStage);
        #pragma unroll
        for (int q = 0; q < 5; q++) {
            int w = t + q * NT;
            if (w < nv) s4[w] = c4[w];
        }
    }
    __syncthreads();

    float cv[HID];
    {
        const float4* s4 = reinterpret_cast<const float4*>(sStage) + t * 5;
        #pragma unroll
        for (int q = 0; q < 5; q++) {            // addr granule 5t+q: conflict-free
            float4 cc = s4[q];
            cv[4 * q + 0] = cc.x; cv[4 * q + 1] = cc.y;
            cv[4 * q + 2] = cc.z; cv[4 * q + 3] = cc.w;
        }
    }
    __syncthreads();

    // ---- stage h0 into the same buffer ----
    {
        const float4* h4 = reinterpret_cast<const float4*>(h0) + (size_t)base * 5;
        float4* s4 = reinterpret_cast<float4*>(sStage);
        #pragma unroll
        for (int q = 0; q < 5; q++) {
            int w = t + q * NT;
            if (w < nv) s4[w] = h4[w];
        }
    }
    __syncthreads();

    if (!active) return;

    // h-row zero test (values live in smem for the cold path)
    float habs = 0.0f;
    {
        const float4* s4 = reinterpret_cast<const float4*>(sStage) + t * 5;
        #pragma unroll
        for (int q = 0; q < 5; q++) {
            float4 hh = s4[q];
            habs += fabsf(hh.x) + fabsf(hh.y) + fabsf(hh.z) + fabsf(hh.w);
        }
    }
    const bool hzero = (habs == 0.0f);

    float acc = cW[260];

    if (__builtin_expect(hzero, 1)) {
        // ---- fast path: h0 row exactly zero -> no W_hh matvec ----
        // All weights are constant-bank FFMA operands: no load instructions.
        #pragma unroll
        for (int k = 0; k < HID; k++) {
            float zi = fmaf(cW[k],       g, fmaf(cW[20 + k],  p, cW[40 + k]));  // halved
            float zg = fmaf(cW[60 + k],  g, fmaf(cW[80 + k],  p, cW[100 + k]));
            float zo = fmaf(cW[120 + k], g, fmaf(cW[140 + k], p, cW[160 + k])); // halved

            float ik = sig_from_half(zi);
            float gk = tanh_ap(zg);
            float ok = sig_from_half(zo);

            float c1 = ik * gk;
            float ck = cv[k];
            if (ck != 0.0f) {
                float zf = fmaf(cW[180 + k], g, fmaf(cW[200 + k], p, cW[220 + k])); // halved
                c1 = fmaf(sig_from_half(zf), ck, c1);
            }
            acc = fmaf(ok * tanh_ap(c1), cW[240 + k], acc);
        }
    } else {
        // ---- general path: full W_hh matvec (cold; W_hh via L2) ----
        const float* sHrow = sStage + t * HID;
        #pragma unroll 1
        for (int k = 0; k < HID; k++) {
            float zi = fmaf(cW[k],       g, fmaf(cW[20 + k],  p, cW[40 + k]));  // halved
            float zg = fmaf(cW[60 + k],  g, fmaf(cW[80 + k],  p, cW[100 + k]));
            float zo = fmaf(cW[120 + k], g, fmaf(cW[140 + k], p, cW[160 + k])); // halved
            float zf = fmaf(cW[180 + k], g, fmaf(cW[200 + k], p, cW[220 + k])); // halved
            const int ri = k, rf = 20 + k, rg = 40 + k, ro = 60 + k;
            #pragma unroll 1
            for (int m = 0; m < HID; m++) {
                float hm = sHrow[m];
                zi = fmaf(0.5f * __ldg(&W_hh[ri * HID + m]), hm, zi);
                zf = fmaf(0.5f * __ldg(&W_hh[rf * HID + m]), hm, zf);
                zg = fmaf(       __ldg(&W_hh[rg * HID + m]), hm, zg);
                zo = fmaf(0.5f * __ldg(&W_hh[ro * HID + m]), hm, zo);
            }
            float ik = sig_from_half(zi);
            float fk = sig_from_half(zf);
            float gk = tanh_ap(zg);
            float ok = sig_from_half(zo);
            float c1 = fmaf(fk, cv[k], ik * gk);
            acc = fmaf(ok * tanh_ap(c1), cW[240 + k], acc);
        }
    }

    out[i] = acc;
}

extern "C" void kernel_launch(void* const* d_in, const int* in_sizes, int n_in,
                              void* d_out, int out_size)
{
    const float* params = (const float*)d_in[0];
    const float* grads  = (const float*)d_in[1];
    const float* h0     = (const float*)d_in[2];
    const float* c0     = (const float*)d_in[3];
    const float* W_ih   = (const float*)d_in[4];
    const float* W_hh   = (const float*)d_in[5];
    const float* b_ih   = (const float*)d_in[6];
    const float* b_hh   = (const float*)d_in[7];
    const float* W_out  = (const float*)d_in[8];
    const float* b_out  = (const float*)d_in[9];
    float* out = (float*)d_out;

    int n = in_sizes[0];

    // 1) compute transformed weights into a __device__ buffer
    prep_kernel<<<1, 32>>>(W_ih, b_ih, b_hh, W_out, b_out);

    // 2) copy them into the constant bank.
    //    CRITICAL FIX vs R5: resolve the *device* address of dPrep — the bare
    //    symbol name on the host is the shadow address and the copy fails.
    void* dprep_ptr = nullptr;
    cudaGetSymbolAddress(&dprep_ptr, dPrep);          // host query, capture-safe
    cudaMemcpyToSymbolAsync(cW, dprep_ptr, CW_SIZE * sizeof(float), 0,
                            cudaMemcpyDeviceToDevice, 0);

    // 3) main kernel reads weights as FFMA constant-bank operands
    int blocks = (n + NT - 1) / NT;
    lstm_opt_kernel<<<blocks, NT>>>(params, grads, h0, c0, W_hh, out, n);
}

// round 7
// speedup vs baseline: 1.8775x; 1.0214x over previous
#include <cuda_runtime.h>
#include <cuda_bf16.h>
#include <cstdint>

#define HID 20
#define NT 256

// Transformed-weight layout (261 floats):
//   [0]   wi_g*0.5   [20] wi_p*0.5  [40] (b_ih+b_hh)_i*0.5
//   [60]  wg_g       [80] wg_p      [100] (b)_g
//   [120] wo_g*0.5   [140] wo_p*0.5 [160] (b)_o*0.5
//   [180] wf_g*0.5   [200] wf_p*0.5 [220] (b)_f*0.5
//   [240] W_out      [260] b_out
#define CW_SIZE 261
__constant__ float cW[CW_SIZE];

__device__ __forceinline__ float tanh_ap(float x) {
    float y;
    asm("tanh.approx.f32 %0, %1;" : "=f"(y) : "f"(x));
    return y;
}
// sigmoid(z) where zh = 0.5*z was computed with pre-halved weights
__device__ __forceinline__ float sig_from_half(float zh) {
    return fmaf(0.5f, tanh_ap(zh), 0.5f);
}

// Writes the transformed weights DIRECTLY into cW's backing storage (global-
// space alias from cudaGetSymbolAddress) — same memory cudaMemcpyToSymbol
// writes; visibility to the next launch is guaranteed by the per-launch cache
// flush. Saves the separate memcpy graph node.
__global__ void prep_kernel(const float* __restrict__ W_ih,
                            const float* __restrict__ b_ih,
                            const float* __restrict__ b_hh,
                            const float* __restrict__ W_out,
                            const float* __restrict__ b_out,
                            float* __restrict__ cw)
{
    const int k = threadIdx.x;
    if (k < HID) {
        const int rf = 20 + k, rg = 40 + k, ro = 60 + k;
        cw[k]        = 0.5f * W_ih[2 * k];
        cw[20 + k]   = 0.5f * W_ih[2 * k + 1];
        cw[40 + k]   = 0.5f * (b_ih[k] + b_hh[k]);
        cw[60 + k]   = W_ih[2 * rg];
        cw[80 + k]   = W_ih[2 * rg + 1];
        cw[100 + k]  = b_ih[rg] + b_hh[rg];
        cw[120 + k]  = 0.5f * W_ih[2 * ro];
        cw[140 + k]  = 0.5f * W_ih[2 * ro + 1];
        cw[160 + k]  = 0.5f * (b_ih[ro] + b_hh[ro]);
        cw[180 + k]  = 0.5f * W_ih[2 * rf];
        cw[200 + k]  = 0.5f * W_ih[2 * rf + 1];
        cw[220 + k]  = 0.5f * (b_ih[rf] + b_hh[rf]);
        cw[240 + k]  = W_out[k];
    }
    if (k == 0) cw[260] = b_out[0];
}

__global__ void __launch_bounds__(NT, 5)
lstm_opt_kernel(const float* __restrict__ params,
                const float* __restrict__ grads,
                const float* __restrict__ h0,
                const float* __restrict__ c0,
                const float* __restrict__ W_hh,   // [80,20] (cold general path)
                float* __restrict__ out,
                int n)
{
    // c0 and h0 tiles staged concurrently via TMA bulk copies.
    __shared__ alignas(128) float sC[NT * HID];   // 20 KB
    __shared__ alignas(128) float sH[NT * HID];   // 20 KB
    __shared__ alignas(8) unsigned long long mbar;

    const int t    = threadIdx.x;
    const int base = blockIdx.x * NT;
    const int rows = min(NT, n - base);
    const bool active = (t < rows);
    const int i = base + t;

    uint32_t mbar_a;
    asm("{ .reg .u64 tmp; cvta.to.shared.u64 tmp, %1; cvt.u32.u64 %0, tmp; }"
        : "=r"(mbar_a) : "l"(&mbar));
    uint32_t sC_a;
    asm("{ .reg .u64 tmp; cvta.to.shared.u64 tmp, %1; cvt.u32.u64 %0, tmp; }"
        : "=r"(sC_a) : "l"(sC));
    uint32_t sH_a;
    asm("{ .reg .u64 tmp; cvta.to.shared.u64 tmp, %1; cvt.u32.u64 %0, tmp; }"
        : "=r"(sH_a) : "l"(sH));

    if (t == 0) {
        asm volatile("mbarrier.init.shared.b64 [%0], %1;"
                     :: "r"(mbar_a), "r"(1u) : "memory");
    }
    __syncthreads();   // mbar visible to all before anyone waits

    // scalar inputs (independent of staging; overlap with TMA)
    float g = 0.0f, p = 0.0f;
    if (active) { g = grads[i]; p = params[i]; }

    if (t == 0) {
        const uint32_t bytes = (uint32_t)rows * HID * 4u;   // multiple of 16
        asm volatile("mbarrier.arrive.expect_tx.shared.b64 _, [%0], %1;"
                     :: "r"(mbar_a), "r"(2u * bytes) : "memory");
        const float* gC = c0 + (size_t)base * HID;
        const float* gH = h0 + (size_t)base * HID;
        asm volatile("cp.async.bulk.shared::cluster.global.mbarrier::complete_tx::bytes "
                     "[%0], [%1], %2, [%3];"
                     :: "r"(sC_a), "l"(gC), "r"(bytes), "r"(mbar_a) : "memory");
        asm volatile("cp.async.bulk.shared::cluster.global.mbarrier::complete_tx::bytes "
                     "[%0], [%1], %2, [%3];"
                     :: "r"(sH_a), "l"(gH), "r"(bytes), "r"(mbar_a) : "memory");
    }

    // wait (acquire) for both tiles, phase parity 0
    {
        uint32_t done;
        asm volatile(
            "{\n\t"
            ".reg .pred P;\n\t"
            "WAIT_%=:\n\t"
            "mbarrier.try_wait.parity.acquire.cta.shared::cta.b64 P, [%1], %2, 0x989680;\n\t"
            "selp.b32 %0, 1, 0, P;\n\t"
            "@!P bra WAIT_%=;\n\t"
            "}"
            : "=r"(done) : "r"(mbar_a), "r"(0u) : "memory");
    }

    if (!active) return;

    // read own c-row (float4, granule stride 5 -> conflict-free)
    float cv[HID];
    {
        const float4* s4 = reinterpret_cast<const float4*>(sC) + t * 5;
        #pragma unroll
        for (int q = 0; q < 5; q++) {
            float4 cc = s4[q];
            cv[4 * q + 0] = cc.x; cv[4 * q + 1] = cc.y;
            cv[4 * q + 2] = cc.z; cv[4 * q + 3] = cc.w;
        }
    }

    // h-row zero test
    float habs = 0.0f;
    {
        const float4* s4 = reinterpret_cast<const float4*>(sH) + t * 5;
        #pragma unroll
        for (int q = 0; q < 5; q++) {
            float4 hh = s4[q];
            habs += fabsf(hh.x) + fabsf(hh.y) + fabsf(hh.z) + fabsf(hh.w);
        }
    }
    const bool hzero = (habs == 0.0f);

    float acc = cW[260];

    if (__builtin_expect(hzero, 1)) {
        // ---- fast path: h0 row exactly zero -> no W_hh matvec ----
        // All weights are constant-bank FFMA operands: no load instructions.
        #pragma unroll
        for (int k = 0; k < HID; k++) {
            float zi = fmaf(cW[k],       g, fmaf(cW[20 + k],  p, cW[40 + k]));  // halved
            float zg = fmaf(cW[60 + k],  g, fmaf(cW[80 + k],  p, cW[100 + k]));
            float zo = fmaf(cW[120 + k], g, fmaf(cW[140 + k], p, cW[160 + k])); // halved

            float ik = sig_from_half(zi);
            float gk = tanh_ap(zg);
            float ok = sig_from_half(zo);

            float c1 = ik * gk;
            float ck = cv[k];
            if (ck != 0.0f) {
                float zf = fmaf(cW[180 + k], g, fmaf(cW[200 + k], p, cW[220 + k])); // halved
                c1 = fmaf(sig_from_half(zf), ck, c1);
            }
            acc = fmaf(ok * tanh_ap(c1), cW[240 + k], acc);
        }
    } else {
        // ---- general path: full W_hh matvec (cold; W_hh via L2) ----
        const float* sHrow = sH + t * HID;
        #pragma unroll 1
        for (int k = 0; k < HID; k++) {
            float zi = fmaf(cW[k],       g, fmaf(cW[20 + k],  p, cW[40 + k]));  // halved
            float zg = fmaf(cW[60 + k],  g, fmaf(cW[80 + k],  p, cW[100 + k]));
            float zo = fmaf(cW[120 + k], g, fmaf(cW[140 + k], p, cW[160 + k])); // halved
            float zf = fmaf(cW[180 + k], g, fmaf(cW[200 + k], p, cW[220 + k])); // halved
            const int ri = k, rf = 20 + k, rg = 40 + k, ro = 60 + k;
            #pragma unroll 1
            for (int m = 0; m < HID; m++) {
                float hm = sHrow[m];
                zi = fmaf(0.5f * __ldg(&W_hh[ri * HID + m]), hm, zi);
                zf = fmaf(0.5f * __ldg(&W_hh[rf * HID + m]), hm, zf);
                zg = fmaf(       __ldg(&W_hh[rg * HID + m]), hm, zg);
                zo = fmaf(0.5f * __ldg(&W_hh[ro * HID + m]), hm, zo);
            }
            float ik = sig_from_half(zi);
            float fk = sig_from_half(zf);
            float gk = tanh_ap(zg);
            float ok = sig_from_half(zo);
            float c1 = fmaf(fk, cv[k], ik * gk);
            acc = fmaf(ok * tanh_ap(c1), cW[240 + k], acc);
        }
    }

    out[i] = acc;
}

extern "C" void kernel_launch(void* const* d_in, const int* in_sizes, int n_in,
                              void* d_out, int out_size)
{
    const float* params = (const float*)d_in[0];
    const float* grads  = (const float*)d_in[1];
    const float* h0     = (const float*)d_in[2];
    const float* c0     = (const float*)d_in[3];
    const float* W_ih   = (const float*)d_in[4];
    const float* W_hh   = (const float*)d_in[5];
    const float* b_ih   = (const float*)d_in[6];
    const float* b_hh   = (const float*)d_in[7];
    const float* W_out  = (const float*)d_in[8];
    const float* b_out  = (const float*)d_in[9];
    float* out = (float*)d_out;

    int n = in_sizes[0];

    // prep writes straight into cW's device backing store (no memcpy node)
    void* cw_ptr = nullptr;
    cudaGetSymbolAddress(&cw_ptr, cW);     // host-side query, capture-safe
    prep_kernel<<<1, 32>>>(W_ih, b_ih, b_hh, W_out, b_out, (float*)cw_ptr);

    int blocks = (n + NT - 1) / NT;
    lstm_opt_kernel<<<blocks, NT>>>(params, grads, h0, c0, W_hh, out, n);
}